// round 12
// baseline (speedup 1.0000x reference)
#include <cuda_runtime.h>
#include <cuda_bf16.h>
#include <cstdint>

#define N_NODES 50000
#define N_EDGES 800000
#define D 64
#define D2 128

#define SCAN_BLK 1024
#define NBLK_SCAN 49

#define TILE_M 128
#define N_TILES ((N_NODES + TILE_M - 1) / TILE_M)   // 391

// GEMM smem layout: bf16 tiles, row stride 272B -> conflict-free ldmatrix/STS.
#define ASTRIDE 272
#define SM_AH 0
#define SM_AM (SM_AH + TILE_M * ASTRIDE)     // 34816
#define SM_BH (SM_AM + TILE_M * ASTRIDE)     // 69632
#define SM_BM (SM_BH + D * ASTRIDE)          // 87040
#define SM_TOTAL (SM_BM + D * ASTRIDE)       // 104448 -> 2 CTAs/SM

#define GATHER_BLOCKS 592

// ---------------------------------------------------------------------------
// Scratch
// ---------------------------------------------------------------------------
struct __align__(8) EdgeRec { int s; float w; };

__device__ int     g_count[N_NODES];
__device__ int     g_start[N_NODES];
__device__ int     g_cursor[N_NODES];
__device__ int     g_total;
__device__ EdgeRec g_edge[N_EDGES];
__device__ float   g_hn[N_NODES * D];   // normalized neighbor mean

// ---------------------------------------------------------------------------
// helpers
// ---------------------------------------------------------------------------
__device__ __forceinline__ uint32_t s2u(const void* p) {
    uint32_t a;
    asm("{ .reg .u64 t; cvta.to.shared.u64 t, %1; cvt.u32.u64 %0, t; }" : "=r"(a) : "l"(p));
    return a;
}

__device__ __forceinline__ void ldm_x4(uint32_t& r0, uint32_t& r1,
                                       uint32_t& r2, uint32_t& r3, uint32_t a) {
    asm volatile("ldmatrix.sync.aligned.m8n8.x4.shared.b16 {%0,%1,%2,%3}, [%4];"
                 : "=r"(r0), "=r"(r1), "=r"(r2), "=r"(r3) : "r"(a));
}
__device__ __forceinline__ void ldm_x2(uint32_t& r0, uint32_t& r1, uint32_t a) {
    asm volatile("ldmatrix.sync.aligned.m8n8.x2.shared.b16 {%0,%1}, [%2];"
                 : "=r"(r0), "=r"(r1) : "r"(a));
}
__device__ __forceinline__ void mma16816(float* c, const uint32_t* a,
                                         uint32_t b0, uint32_t b1) {
    asm volatile("mma.sync.aligned.m16n8k16.row.col.f32.bf16.bf16.f32 "
                 "{%0,%1,%2,%3}, {%4,%5,%6,%7}, {%8,%9}, {%0,%1,%2,%3};"
                 : "+f"(c[0]), "+f"(c[1]), "+f"(c[2]), "+f"(c[3])
                 : "r"(a[0]), "r"(a[1]), "r"(a[2]), "r"(a[3]), "r"(b0), "r"(b1));
}

__device__ __forceinline__ void split8(const float* v, uint4& uh, uint4& um) {
    uint32_t hs[8], ms[8];
    #pragma unroll
    for (int i = 0; i < 8; i++) {
        __nv_bfloat16 hb = __float2bfloat16(v[i]);
        float rem = v[i] - __bfloat162float(hb);
        __nv_bfloat16 mb = __float2bfloat16(rem);
        hs[i] = (uint32_t)__bfloat16_as_ushort(hb);
        ms[i] = (uint32_t)__bfloat16_as_ushort(mb);
    }
    uh = make_uint4(hs[0] | (hs[1] << 16), hs[2] | (hs[3] << 16),
                    hs[4] | (hs[5] << 16), hs[6] | (hs[7] << 16));
    um = make_uint4(ms[0] | (ms[1] << 16), ms[2] | (ms[3] << 16),
                    ms[4] | (ms[5] << 16), ms[6] | (ms[7] << 16));
}

// ---------------------------------------------------------------------------
// K1: histogram (4 edges/thread); resets g_total
// ---------------------------------------------------------------------------
__global__ void hist_kernel(const int* __restrict__ dst) {
    int t = blockIdx.x * blockDim.x + threadIdx.x;
    if (t == 0) g_total = 0;
    if (t >= N_EDGES / 4) return;
    int4 d4 = reinterpret_cast<const int4*>(dst)[t];
    atomicAdd(&g_count[d4.x], 1);
    atomicAdd(&g_count[d4.y], 1);
    atomicAdd(&g_count[d4.z], 1);
    atomicAdd(&g_count[d4.w], 1);
}

// ---------------------------------------------------------------------------
// K2: reserve CSR slices (block scan + atomic base claim)
// ---------------------------------------------------------------------------
__global__ __launch_bounds__(SCAN_BLK) void reserve_kernel() {
    __shared__ int sh[SCAN_BLK];
    __shared__ int base_sh;
    int t = threadIdx.x;
    int i = blockIdx.x * SCAN_BLK + t;
    int c = (i < N_NODES) ? g_count[i] : 0;
    sh[t] = c;
    __syncthreads();
    for (int d = 1; d < SCAN_BLK; d <<= 1) {
        int v = (t >= d) ? sh[t - d] : 0;
        __syncthreads();
        sh[t] += v;
        __syncthreads();
    }
    if (t == SCAN_BLK - 1) base_sh = atomicAdd(&g_total, sh[t]);
    __syncthreads();
    if (i < N_NODES) {
        int v = base_sh + sh[t] - c;
        g_start[i]  = v;
        g_cursor[i] = v;
    }
}

// ---------------------------------------------------------------------------
// K3: position scatter (4 edges/thread)
// ---------------------------------------------------------------------------
__global__ void pos_kernel(const int* __restrict__ src,
                           const int* __restrict__ dst,
                           const float* __restrict__ w) {
    int t = blockIdx.x * blockDim.x + threadIdx.x;
    if (t >= N_EDGES / 4) return;
    int4   s4 = reinterpret_cast<const int4*>(src)[t];
    int4   d4 = reinterpret_cast<const int4*>(dst)[t];
    float4 w4 = reinterpret_cast<const float4*>(w)[t];
    int p0 = atomicAdd(&g_cursor[d4.x], 1);
    int p1 = atomicAdd(&g_cursor[d4.y], 1);
    int p2 = atomicAdd(&g_cursor[d4.z], 1);
    int p3 = atomicAdd(&g_cursor[d4.w], 1);
    EdgeRec r;
    r.s = s4.x; r.w = w4.x; g_edge[p0] = r;
    r.s = s4.y; r.w = w4.y; g_edge[p1] = r;
    r.s = s4.z; r.w = w4.z; g_edge[p2] = r;
    r.s = s4.w; r.w = w4.w; g_edge[p3] = r;
}

// ---------------------------------------------------------------------------
// K4: gather -> normalized h_N. GRID-STRIDE warp-per-node (592 CTAs x 8
// warps; each warp ~10.6 nodes): amortizes CTA spin-up, averages degree-
// variance tail, overlaps consecutive nodes' memory chains. Lane-parallel
// rec bulk-load + shfl broadcast. Zeroes g_count (invariant).
// ---------------------------------------------------------------------------
__global__ __launch_bounds__(256) void gather_kernel(const float* __restrict__ h) {
    int warp = threadIdx.x >> 5;
    int lane = threadIdx.x & 31;
    const float2* __restrict__ h2 = reinterpret_cast<const float2*>(h);

    int gw = blockIdx.x * 8 + warp;
    int nwarps = gridDim.x * 8;

    for (int n = gw; n < N_NODES; n += nwarps) {
        int beg = g_start[n];
        int cnt = g_count[n];
        float ax = 0.f, ay = 0.f;

        for (int base = 0; base < cnt; base += 32) {
            int m = cnt - base;
            if (m > 32) m = 32;
            int   rs = 0;
            float rw = 0.f;
            if (lane < m) {
                EdgeRec r = g_edge[beg + base + lane];
                rs = r.s;
                rw = r.w;
            }
            int j = 0;
            for (; j + 3 < m; j += 4) {
                int   s0 = __shfl_sync(0xffffffffu, rs, j);
                int   s1 = __shfl_sync(0xffffffffu, rs, j + 1);
                int   s2 = __shfl_sync(0xffffffffu, rs, j + 2);
                int   s3 = __shfl_sync(0xffffffffu, rs, j + 3);
                float w0 = __shfl_sync(0xffffffffu, rw, j);
                float w1 = __shfl_sync(0xffffffffu, rw, j + 1);
                float w2 = __shfl_sync(0xffffffffu, rw, j + 2);
                float w3 = __shfl_sync(0xffffffffu, rw, j + 3);
                float2 h0 = h2[(size_t)s0 * 32 + lane];
                float2 h1 = h2[(size_t)s1 * 32 + lane];
                float2 hv = h2[(size_t)s2 * 32 + lane];
                float2 h3 = h2[(size_t)s3 * 32 + lane];
                ax += h0.x * w0 + h1.x * w1 + hv.x * w2 + h3.x * w3;
                ay += h0.y * w0 + h1.y * w1 + hv.y * w2 + h3.y * w3;
            }
            for (; j < m; j++) {
                int   s0 = __shfl_sync(0xffffffffu, rs, j);
                float w0 = __shfl_sync(0xffffffffu, rw, j);
                float2 h0 = h2[(size_t)s0 * 32 + lane];
                ax += h0.x * w0;
                ay += h0.y * w0;
            }
        }

        float inv = 1.0f / fmaxf((float)cnt, 1.0f);
        reinterpret_cast<float2*>(g_hn)[(size_t)n * 32 + lane] =
            make_float2(ax * inv, ay * inv);
        if (lane == 0) g_count[n] = 0;
    }
}

// ---------------------------------------------------------------------------
// K5: HMMA GEMM: out[tile 128, 64] = [h|h_N] @ W^T + b, bf16 3-split.
// ---------------------------------------------------------------------------
__global__ __launch_bounds__(256)
void gemm_kernel(const float* __restrict__ h,
                 const float* __restrict__ W,
                 const float* __restrict__ b,
                 float* __restrict__ out) {
    extern __shared__ char smem[];
    uint32_t sb = s2u(smem);
    int tid = threadIdx.x;
    int wid = tid >> 5;
    int lane = tid & 31;
    int n0 = blockIdx.x * TILE_M;

    // ---- stage B (W -> Bh/Bm) ----
    #pragma unroll
    for (int it = 0; it < 4; it++) {
        int task = tid + 256 * it;
        int r = task >> 4;
        int c = task & 15;
        float v[8];
        const float4* p = reinterpret_cast<const float4*>(W + (size_t)r * D2 + c * 8);
        float4 v0 = p[0], v1 = p[1];
        v[0]=v0.x; v[1]=v0.y; v[2]=v0.z; v[3]=v0.w;
        v[4]=v1.x; v[5]=v1.y; v[6]=v1.z; v[7]=v1.w;
        uint4 uh, um; split8(v, uh, um);
        uint32_t off = (uint32_t)r * ASTRIDE + c * 16;
        *reinterpret_cast<uint4*>(smem + SM_BH + off) = uh;
        *reinterpret_cast<uint4*>(smem + SM_BM + off) = um;
    }

    // ---- stage A ([h|h_N] -> Ah/Am) ----
    #pragma unroll
    for (int it = 0; it < 8; it++) {
        int task = tid + 256 * it;
        int r = task >> 4;
        int c = task & 15;
        int n = n0 + r;
        float v[8];
        if (n < N_NODES) {
            const float* srcp = (c < 8)
                ? (h    + (size_t)n * D + c * 8)
                : (g_hn + (size_t)n * D + (c - 8) * 8);
            const float4* p = reinterpret_cast<const float4*>(srcp);
            float4 v0 = p[0], v1 = p[1];
            v[0]=v0.x; v[1]=v0.y; v[2]=v0.z; v[3]=v0.w;
            v[4]=v1.x; v[5]=v1.y; v[6]=v1.z; v[7]=v1.w;
        } else {
            #pragma unroll
            for (int i = 0; i < 8; i++) v[i] = 0.f;
        }
        uint4 uh, um; split8(v, uh, um);
        uint32_t off = (uint32_t)r * ASTRIDE + c * 16;
        *reinterpret_cast<uint4*>(smem + SM_AH + off) = uh;
        *reinterpret_cast<uint4*>(smem + SM_AM + off) = um;
    }
    __syncthreads();

    // ---- compute ----
    float c[8][4];
    #pragma unroll
    for (int nc = 0; nc < 8; nc++)
        #pragma unroll
        for (int i = 0; i < 4; i++) c[nc][i] = 0.f;

    uint32_t arow = (lane & 7) + ((lane >> 3) & 1) * 8;
    uint32_t asel = (lane >> 4) * 16;
    uint32_t brow = lane & 7;
    uint32_t bsel = ((lane >> 3) & 1) * 16;

    #pragma unroll
    for (int ks = 0; ks < 8; ks++) {
        uint32_t acol = ks * 32 + asel;
        uint32_t aaddr = sb + SM_AH + (wid * 16 + arow) * ASTRIDE + acol;
        uint32_t ah[4], am[4];
        ldm_x4(ah[0], ah[1], ah[2], ah[3], aaddr);
        ldm_x4(am[0], am[1], am[2], am[3], aaddr + (SM_AM - SM_AH));

        uint32_t bcol = ks * 32 + bsel;
        #pragma unroll
        for (int nc = 0; nc < 8; nc++) {
            uint32_t baddr = sb + SM_BH + (nc * 8 + brow) * ASTRIDE + bcol;
            uint32_t bh0, bh1, bm0, bm1;
            ldm_x2(bh0, bh1, baddr);
            ldm_x2(bm0, bm1, baddr + (SM_BM - SM_BH));
            mma16816(c[nc], ah, bh0, bh1);   // hh
            mma16816(c[nc], ah, bm0, bm1);   // hm
            mma16816(c[nc], am, bh0, bh1);   // mh
        }
    }

    // ---- epilogue: bias + store ----
    int r0 = n0 + wid * 16 + (lane >> 2);
    int r1 = r0 + 8;
    int cb = (lane & 3) * 2;
    #pragma unroll
    for (int nc = 0; nc < 8; nc++) {
        int col = nc * 8 + cb;
        float2 bv = *reinterpret_cast<const float2*>(b + col);
        if (r0 < N_NODES)
            *reinterpret_cast<float2*>(out + (size_t)r0 * D + col) =
                make_float2(c[nc][0] + bv.x, c[nc][1] + bv.y);
        if (r1 < N_NODES)
            *reinterpret_cast<float2*>(out + (size_t)r1 * D + col) =
                make_float2(c[nc][2] + bv.x, c[nc][3] + bv.y);
    }
}

// ---------------------------------------------------------------------------
// Launch — 5 kernels
// ---------------------------------------------------------------------------
extern "C" void kernel_launch(void* const* d_in, const int* in_sizes, int n_in,
                              void* d_out, int out_size) {
    const float* h   = (const float*)d_in[0];
    const float* w   = (const float*)d_in[1];
    const int*   src = (const int*)  d_in[2];
    const int*   dst = (const int*)  d_in[3];
    const float* W   = (const float*)d_in[4];
    const float* b   = (const float*)d_in[5];
    float* out = (float*)d_out;

    (void)in_sizes; (void)n_in; (void)out_size;

    static bool attr_set = false;
    if (!attr_set) {
        cudaFuncSetAttribute(gemm_kernel,
                             cudaFuncAttributeMaxDynamicSharedMemorySize, SM_TOTAL);
        attr_set = true;
    }

    hist_kernel<<<(N_EDGES / 4 + 255) / 256, 256>>>(dst);
    reserve_kernel<<<NBLK_SCAN, SCAN_BLK>>>();
    pos_kernel<<<(N_EDGES / 4 + 255) / 256, 256>>>(src, dst, w);
    gather_kernel<<<GATHER_BLOCKS, 256>>>(h);
    gemm_kernel<<<N_TILES, 256, SM_TOTAL>>>(h, W, b, out);
}

// round 13
// speedup vs baseline: 1.1810x; 1.1810x over previous
#include <cuda_runtime.h>
#include <cuda_bf16.h>
#include <cstdint>

#define N_NODES 50000
#define N_EDGES 800000
#define D 64
#define D2 128

#define SCAN_BLK 1024
#define NBLK_SCAN 49

#define TILE_M 128
#define N_TILES ((N_NODES + TILE_M - 1) / TILE_M)   // 391

// GEMM smem layout: bf16 tiles, row stride 272B -> conflict-free ldmatrix/STS.
#define ASTRIDE 272
#define SM_AH 0
#define SM_AM (SM_AH + TILE_M * ASTRIDE)     // 34816
#define SM_BH (SM_AM + TILE_M * ASTRIDE)     // 69632
#define SM_BM (SM_BH + D * ASTRIDE)          // 87040
#define SM_TOTAL (SM_BM + D * ASTRIDE)       // 104448 -> 2 CTAs/SM

// 8 CTAs/SM x 148 SMs = full residency in ONE wave (regs=32, smem=0 -> the
// occupancy limit is 2048 thr/SM). R12's 592 halved resident warps; this
// keeps grid-stride amortization AND 64 warps/SM.
#define GATHER_BLOCKS 1184

// ---------------------------------------------------------------------------
// Scratch
// ---------------------------------------------------------------------------
struct __align__(8) EdgeRec { int s; float w; };

__device__ int     g_count[N_NODES];
__device__ int     g_start[N_NODES];
__device__ int     g_cursor[N_NODES];
__device__ int     g_total;
__device__ EdgeRec g_edge[N_EDGES];
__device__ float   g_hn[N_NODES * D];   // normalized neighbor mean

// ---------------------------------------------------------------------------
// helpers
// ---------------------------------------------------------------------------
__device__ __forceinline__ uint32_t s2u(const void* p) {
    uint32_t a;
    asm("{ .reg .u64 t; cvta.to.shared.u64 t, %1; cvt.u32.u64 %0, t; }" : "=r"(a) : "l"(p));
    return a;
}

__device__ __forceinline__ void ldm_x4(uint32_t& r0, uint32_t& r1,
                                       uint32_t& r2, uint32_t& r3, uint32_t a) {
    asm volatile("ldmatrix.sync.aligned.m8n8.x4.shared.b16 {%0,%1,%2,%3}, [%4];"
                 : "=r"(r0), "=r"(r1), "=r"(r2), "=r"(r3) : "r"(a));
}
__device__ __forceinline__ void ldm_x2(uint32_t& r0, uint32_t& r1, uint32_t a) {
    asm volatile("ldmatrix.sync.aligned.m8n8.x2.shared.b16 {%0,%1}, [%2];"
                 : "=r"(r0), "=r"(r1) : "r"(a));
}
__device__ __forceinline__ void mma16816(float* c, const uint32_t* a,
                                         uint32_t b0, uint32_t b1) {
    asm volatile("mma.sync.aligned.m16n8k16.row.col.f32.bf16.bf16.f32 "
                 "{%0,%1,%2,%3}, {%4,%5,%6,%7}, {%8,%9}, {%0,%1,%2,%3};"
                 : "+f"(c[0]), "+f"(c[1]), "+f"(c[2]), "+f"(c[3])
                 : "r"(a[0]), "r"(a[1]), "r"(a[2]), "r"(a[3]), "r"(b0), "r"(b1));
}

__device__ __forceinline__ void split8(const float* v, uint4& uh, uint4& um) {
    uint32_t hs[8], ms[8];
    #pragma unroll
    for (int i = 0; i < 8; i++) {
        __nv_bfloat16 hb = __float2bfloat16(v[i]);
        float rem = v[i] - __bfloat162float(hb);
        __nv_bfloat16 mb = __float2bfloat16(rem);
        hs[i] = (uint32_t)__bfloat16_as_ushort(hb);
        ms[i] = (uint32_t)__bfloat16_as_ushort(mb);
    }
    uh = make_uint4(hs[0] | (hs[1] << 16), hs[2] | (hs[3] << 16),
                    hs[4] | (hs[5] << 16), hs[6] | (hs[7] << 16));
    um = make_uint4(ms[0] | (ms[1] << 16), ms[2] | (ms[3] << 16),
                    ms[4] | (ms[5] << 16), ms[6] | (ms[7] << 16));
}

// ---------------------------------------------------------------------------
// K1: histogram (4 edges/thread); resets g_total
// ---------------------------------------------------------------------------
__global__ void hist_kernel(const int* __restrict__ dst) {
    int t = blockIdx.x * blockDim.x + threadIdx.x;
    if (t == 0) g_total = 0;
    if (t >= N_EDGES / 4) return;
    int4 d4 = reinterpret_cast<const int4*>(dst)[t];
    atomicAdd(&g_count[d4.x], 1);
    atomicAdd(&g_count[d4.y], 1);
    atomicAdd(&g_count[d4.z], 1);
    atomicAdd(&g_count[d4.w], 1);
}

// ---------------------------------------------------------------------------
// K2: reserve CSR slices (block scan + atomic base claim)
// ---------------------------------------------------------------------------
__global__ __launch_bounds__(SCAN_BLK) void reserve_kernel() {
    __shared__ int sh[SCAN_BLK];
    __shared__ int base_sh;
    int t = threadIdx.x;
    int i = blockIdx.x * SCAN_BLK + t;
    int c = (i < N_NODES) ? g_count[i] : 0;
    sh[t] = c;
    __syncthreads();
    for (int d = 1; d < SCAN_BLK; d <<= 1) {
        int v = (t >= d) ? sh[t - d] : 0;
        __syncthreads();
        sh[t] += v;
        __syncthreads();
    }
    if (t == SCAN_BLK - 1) base_sh = atomicAdd(&g_total, sh[t]);
    __syncthreads();
    if (i < N_NODES) {
        int v = base_sh + sh[t] - c;
        g_start[i]  = v;
        g_cursor[i] = v;
    }
}

// ---------------------------------------------------------------------------
// K3: position scatter (4 edges/thread)
// ---------------------------------------------------------------------------
__global__ void pos_kernel(const int* __restrict__ src,
                           const int* __restrict__ dst,
                           const float* __restrict__ w) {
    int t = blockIdx.x * blockDim.x + threadIdx.x;
    if (t >= N_EDGES / 4) return;
    int4   s4 = reinterpret_cast<const int4*>(src)[t];
    int4   d4 = reinterpret_cast<const int4*>(dst)[t];
    float4 w4 = reinterpret_cast<const float4*>(w)[t];
    int p0 = atomicAdd(&g_cursor[d4.x], 1);
    int p1 = atomicAdd(&g_cursor[d4.y], 1);
    int p2 = atomicAdd(&g_cursor[d4.z], 1);
    int p3 = atomicAdd(&g_cursor[d4.w], 1);
    EdgeRec r;
    r.s = s4.x; r.w = w4.x; g_edge[p0] = r;
    r.s = s4.y; r.w = w4.y; g_edge[p1] = r;
    r.s = s4.z; r.w = w4.z; g_edge[p2] = r;
    r.s = s4.w; r.w = w4.w; g_edge[p3] = r;
}

// ---------------------------------------------------------------------------
// K4: gather -> normalized h_N. Grid-stride warp-per-node at FULL residency
// (1184 CTAs = 8/SM). Lane-parallel rec bulk-load + shfl broadcast.
// Zeroes g_count (invariant).
// ---------------------------------------------------------------------------
__global__ __launch_bounds__(256) void gather_kernel(const float* __restrict__ h) {
    int warp = threadIdx.x >> 5;
    int lane = threadIdx.x & 31;
    const float2* __restrict__ h2 = reinterpret_cast<const float2*>(h);

    int gw = blockIdx.x * 8 + warp;
    int nwarps = gridDim.x * 8;

    for (int n = gw; n < N_NODES; n += nwarps) {
        int beg = g_start[n];
        int cnt = g_count[n];
        float ax = 0.f, ay = 0.f;

        for (int base = 0; base < cnt; base += 32) {
            int m = cnt - base;
            if (m > 32) m = 32;
            int   rs = 0;
            float rw = 0.f;
            if (lane < m) {
                EdgeRec r = g_edge[beg + base + lane];
                rs = r.s;
                rw = r.w;
            }
            int j = 0;
            for (; j + 3 < m; j += 4) {
                int   s0 = __shfl_sync(0xffffffffu, rs, j);
                int   s1 = __shfl_sync(0xffffffffu, rs, j + 1);
                int   s2 = __shfl_sync(0xffffffffu, rs, j + 2);
                int   s3 = __shfl_sync(0xffffffffu, rs, j + 3);
                float w0 = __shfl_sync(0xffffffffu, rw, j);
                float w1 = __shfl_sync(0xffffffffu, rw, j + 1);
                float w2 = __shfl_sync(0xffffffffu, rw, j + 2);
                float w3 = __shfl_sync(0xffffffffu, rw, j + 3);
                float2 h0 = h2[(size_t)s0 * 32 + lane];
                float2 h1 = h2[(size_t)s1 * 32 + lane];
                float2 hv = h2[(size_t)s2 * 32 + lane];
                float2 h3 = h2[(size_t)s3 * 32 + lane];
                ax += h0.x * w0 + h1.x * w1 + hv.x * w2 + h3.x * w3;
                ay += h0.y * w0 + h1.y * w1 + hv.y * w2 + h3.y * w3;
            }
            for (; j < m; j++) {
                int   s0 = __shfl_sync(0xffffffffu, rs, j);
                float w0 = __shfl_sync(0xffffffffu, rw, j);
                float2 h0 = h2[(size_t)s0 * 32 + lane];
                ax += h0.x * w0;
                ay += h0.y * w0;
            }
        }

        float inv = 1.0f / fmaxf((float)cnt, 1.0f);
        reinterpret_cast<float2*>(g_hn)[(size_t)n * 32 + lane] =
            make_float2(ax * inv, ay * inv);
        if (lane == 0) g_count[n] = 0;
    }
}

// ---------------------------------------------------------------------------
// K5: HMMA GEMM: out[tile 128, 64] = [h|h_N] @ W^T + b, bf16 3-split.
// ---------------------------------------------------------------------------
__global__ __launch_bounds__(256)
void gemm_kernel(const float* __restrict__ h,
                 const float* __restrict__ W,
                 const float* __restrict__ b,
                 float* __restrict__ out) {
    extern __shared__ char smem[];
    uint32_t sb = s2u(smem);
    int tid = threadIdx.x;
    int wid = tid >> 5;
    int lane = tid & 31;
    int n0 = blockIdx.x * TILE_M;

    // ---- stage B (W -> Bh/Bm) ----
    #pragma unroll
    for (int it = 0; it < 4; it++) {
        int task = tid + 256 * it;
        int r = task >> 4;
        int c = task & 15;
        float v[8];
        const float4* p = reinterpret_cast<const float4*>(W + (size_t)r * D2 + c * 8);
        float4 v0 = p[0], v1 = p[1];
        v[0]=v0.x; v[1]=v0.y; v[2]=v0.z; v[3]=v0.w;
        v[4]=v1.x; v[5]=v1.y; v[6]=v1.z; v[7]=v1.w;
        uint4 uh, um; split8(v, uh, um);
        uint32_t off = (uint32_t)r * ASTRIDE + c * 16;
        *reinterpret_cast<uint4*>(smem + SM_BH + off) = uh;
        *reinterpret_cast<uint4*>(smem + SM_BM + off) = um;
    }

    // ---- stage A ([h|h_N] -> Ah/Am) ----
    #pragma unroll
    for (int it = 0; it < 8; it++) {
        int task = tid + 256 * it;
        int r = task >> 4;
        int c = task & 15;
        int n = n0 + r;
        float v[8];
        if (n < N_NODES) {
            const float* srcp = (c < 8)
                ? (h    + (size_t)n * D + c * 8)
                : (g_hn + (size_t)n * D + (c - 8) * 8);
            const float4* p = reinterpret_cast<const float4*>(srcp);
            float4 v0 = p[0], v1 = p[1];
            v[0]=v0.x; v[1]=v0.y; v[2]=v0.z; v[3]=v0.w;
            v[4]=v1.x; v[5]=v1.y; v[6]=v1.z; v[7]=v1.w;
        } else {
            #pragma unroll
            for (int i = 0; i < 8; i++) v[i] = 0.f;
        }
        uint4 uh, um; split8(v, uh, um);
        uint32_t off = (uint32_t)r * ASTRIDE + c * 16;
        *reinterpret_cast<uint4*>(smem + SM_AH + off) = uh;
        *reinterpret_cast<uint4*>(smem + SM_AM + off) = um;
    }
    __syncthreads();

    // ---- compute ----
    float c[8][4];
    #pragma unroll
    for (int nc = 0; nc < 8; nc++)
        #pragma unroll
        for (int i = 0; i < 4; i++) c[nc][i] = 0.f;

    uint32_t arow = (lane & 7) + ((lane >> 3) & 1) * 8;
    uint32_t asel = (lane >> 4) * 16;
    uint32_t brow = lane & 7;
    uint32_t bsel = ((lane >> 3) & 1) * 16;

    #pragma unroll
    for (int ks = 0; ks < 8; ks++) {
        uint32_t acol = ks * 32 + asel;
        uint32_t aaddr = sb + SM_AH + (wid * 16 + arow) * ASTRIDE + acol;
        uint32_t ah[4], am[4];
        ldm_x4(ah[0], ah[1], ah[2], ah[3], aaddr);
        ldm_x4(am[0], am[1], am[2], am[3], aaddr + (SM_AM - SM_AH));

        uint32_t bcol = ks * 32 + bsel;
        #pragma unroll
        for (int nc = 0; nc < 8; nc++) {
            uint32_t baddr = sb + SM_BH + (nc * 8 + brow) * ASTRIDE + bcol;
            uint32_t bh0, bh1, bm0, bm1;
            ldm_x2(bh0, bh1, baddr);
            ldm_x2(bm0, bm1, baddr + (SM_BM - SM_BH));
            mma16816(c[nc], ah, bh0, bh1);   // hh
            mma16816(c[nc], ah, bm0, bm1);   // hm
            mma16816(c[nc], am, bh0, bh1);   // mh
        }
    }

    // ---- epilogue: bias + store ----
    int r0 = n0 + wid * 16 + (lane >> 2);
    int r1 = r0 + 8;
    int cb = (lane & 3) * 2;
    #pragma unroll
    for (int nc = 0; nc < 8; nc++) {
        int col = nc * 8 + cb;
        float2 bv = *reinterpret_cast<const float2*>(b + col);
        if (r0 < N_NODES)
            *reinterpret_cast<float2*>(out + (size_t)r0 * D + col) =
                make_float2(c[nc][0] + bv.x, c[nc][1] + bv.y);
        if (r1 < N_NODES)
            *reinterpret_cast<float2*>(out + (size_t)r1 * D + col) =
                make_float2(c[nc][2] + bv.x, c[nc][3] + bv.y);
    }
}

// ---------------------------------------------------------------------------
// Launch — 5 kernels
// ---------------------------------------------------------------------------
extern "C" void kernel_launch(void* const* d_in, const int* in_sizes, int n_in,
                              void* d_out, int out_size) {
    const float* h   = (const float*)d_in[0];
    const float* w   = (const float*)d_in[1];
    const int*   src = (const int*)  d_in[2];
    const int*   dst = (const int*)  d_in[3];
    const float* W   = (const float*)d_in[4];
    const float* b   = (const float*)d_in[5];
    float* out = (float*)d_out;

    (void)in_sizes; (void)n_in; (void)out_size;

    static bool attr_set = false;
    if (!attr_set) {
        cudaFuncSetAttribute(gemm_kernel,
                             cudaFuncAttributeMaxDynamicSharedMemorySize, SM_TOTAL);
        attr_set = true;
    }

    hist_kernel<<<(N_EDGES / 4 + 255) / 256, 256>>>(dst);
    reserve_kernel<<<NBLK_SCAN, SCAN_BLK>>>();
    pos_kernel<<<(N_EDGES / 4 + 255) / 256, 256>>>(src, dst, w);
    gather_kernel<<<GATHER_BLOCKS, 256>>>(h);
    gemm_kernel<<<N_TILES, 256, SM_TOTAL>>>(h, W, b, out);
}

// round 14
// speedup vs baseline: 1.2157x; 1.0294x over previous
#include <cuda_runtime.h>
#include <cuda_bf16.h>
#include <cstdint>

#define N_NODES 50000
#define N_EDGES 800000
#define D 64
#define D2 128

#define SCAN_BLK 1024
#define NBLK_SCAN 49

#define TILE_M 128
#define N_TILES ((N_NODES + TILE_M - 1) / TILE_M)   // 391

// GEMM smem layout: bf16 tiles, row stride 272B -> conflict-free ldmatrix/STS.
#define ASTRIDE 272
#define SM_AH 0
#define SM_AM (SM_AH + TILE_M * ASTRIDE)     // 34816
#define SM_BH (SM_AM + TILE_M * ASTRIDE)     // 69632
#define SM_BM (SM_BH + D * ASTRIDE)          // 87040
#define SM_TOTAL (SM_BM + D * ASTRIDE)       // 104448 -> 2 CTAs/SM

#define GATHER_BLOCKS 1184

// ---------------------------------------------------------------------------
// Scratch
// ---------------------------------------------------------------------------
struct __align__(8) EdgeRec { int s; float w; };

__device__ int     g_count[N_NODES];
__device__ int     g_start[N_NODES];
__device__ int     g_cursor[N_NODES];
__device__ int     g_total;
__device__ EdgeRec g_edge[N_EDGES];
__device__ float   g_hn[N_NODES * D];   // normalized neighbor mean

// ---------------------------------------------------------------------------
// helpers
// ---------------------------------------------------------------------------
__device__ __forceinline__ uint32_t s2u(const void* p) {
    uint32_t a;
    asm("{ .reg .u64 t; cvta.to.shared.u64 t, %1; cvt.u32.u64 %0, t; }" : "=r"(a) : "l"(p));
    return a;
}

__device__ __forceinline__ void ldm_x4(uint32_t& r0, uint32_t& r1,
                                       uint32_t& r2, uint32_t& r3, uint32_t a) {
    asm volatile("ldmatrix.sync.aligned.m8n8.x4.shared.b16 {%0,%1,%2,%3}, [%4];"
                 : "=r"(r0), "=r"(r1), "=r"(r2), "=r"(r3) : "r"(a));
}
__device__ __forceinline__ void ldm_x2(uint32_t& r0, uint32_t& r1, uint32_t a) {
    asm volatile("ldmatrix.sync.aligned.m8n8.x2.shared.b16 {%0,%1}, [%2];"
                 : "=r"(r0), "=r"(r1) : "r"(a));
}
__device__ __forceinline__ void mma16816(float* c, const uint32_t* a,
                                         uint32_t b0, uint32_t b1) {
    asm volatile("mma.sync.aligned.m16n8k16.row.col.f32.bf16.bf16.f32 "
                 "{%0,%1,%2,%3}, {%4,%5,%6,%7}, {%8,%9}, {%0,%1,%2,%3};"
                 : "+f"(c[0]), "+f"(c[1]), "+f"(c[2]), "+f"(c[3])
                 : "r"(a[0]), "r"(a[1]), "r"(a[2]), "r"(a[3]), "r"(b0), "r"(b1));
}

__device__ __forceinline__ void split8(const float* v, uint4& uh, uint4& um) {
    uint32_t hs[8], ms[8];
    #pragma unroll
    for (int i = 0; i < 8; i++) {
        __nv_bfloat16 hb = __float2bfloat16(v[i]);
        float rem = v[i] - __bfloat162float(hb);
        __nv_bfloat16 mb = __float2bfloat16(rem);
        hs[i] = (uint32_t)__bfloat16_as_ushort(hb);
        ms[i] = (uint32_t)__bfloat16_as_ushort(mb);
    }
    uh = make_uint4(hs[0] | (hs[1] << 16), hs[2] | (hs[3] << 16),
                    hs[4] | (hs[5] << 16), hs[6] | (hs[7] << 16));
    um = make_uint4(ms[0] | (ms[1] << 16), ms[2] | (ms[3] << 16),
                    ms[4] | (ms[5] << 16), ms[6] | (ms[7] << 16));
}

// ---------------------------------------------------------------------------
// K1: histogram (4 edges/thread); resets g_total
// ---------------------------------------------------------------------------
__global__ void hist_kernel(const int* __restrict__ dst) {
    int t = blockIdx.x * blockDim.x + threadIdx.x;
    if (t == 0) g_total = 0;
    if (t >= N_EDGES / 4) return;
    int4 d4 = reinterpret_cast<const int4*>(dst)[t];
    atomicAdd(&g_count[d4.x], 1);
    atomicAdd(&g_count[d4.y], 1);
    atomicAdd(&g_count[d4.z], 1);
    atomicAdd(&g_count[d4.w], 1);
}

// ---------------------------------------------------------------------------
// K2: reserve CSR slices (block scan + atomic base claim)
// ---------------------------------------------------------------------------
__global__ __launch_bounds__(SCAN_BLK) void reserve_kernel() {
    __shared__ int sh[SCAN_BLK];
    __shared__ int base_sh;
    int t = threadIdx.x;
    int i = blockIdx.x * SCAN_BLK + t;
    int c = (i < N_NODES) ? g_count[i] : 0;
    sh[t] = c;
    __syncthreads();
    for (int d = 1; d < SCAN_BLK; d <<= 1) {
        int v = (t >= d) ? sh[t - d] : 0;
        __syncthreads();
        sh[t] += v;
        __syncthreads();
    }
    if (t == SCAN_BLK - 1) base_sh = atomicAdd(&g_total, sh[t]);
    __syncthreads();
    if (i < N_NODES) {
        int v = base_sh + sh[t] - c;
        g_start[i]  = v;
        g_cursor[i] = v;
    }
}

// ---------------------------------------------------------------------------
// K3: position scatter (4 edges/thread)
// ---------------------------------------------------------------------------
__global__ void pos_kernel(const int* __restrict__ src,
                           const int* __restrict__ dst,
                           const float* __restrict__ w) {
    int t = blockIdx.x * blockDim.x + threadIdx.x;
    if (t >= N_EDGES / 4) return;
    int4   s4 = reinterpret_cast<const int4*>(src)[t];
    int4   d4 = reinterpret_cast<const int4*>(dst)[t];
    float4 w4 = reinterpret_cast<const float4*>(w)[t];
    int p0 = atomicAdd(&g_cursor[d4.x], 1);
    int p1 = atomicAdd(&g_cursor[d4.y], 1);
    int p2 = atomicAdd(&g_cursor[d4.z], 1);
    int p3 = atomicAdd(&g_cursor[d4.w], 1);
    EdgeRec r;
    r.s = s4.x; r.w = w4.x; g_edge[p0] = r;
    r.s = s4.y; r.w = w4.y; g_edge[p1] = r;
    r.s = s4.z; r.w = w4.z; g_edge[p2] = r;
    r.s = s4.w; r.w = w4.w; g_edge[p3] = r;
}

// ---------------------------------------------------------------------------
// K4: gather -> normalized h_N. TWO NODES PER WARP: half-warp per node,
// lane owns a float4 (16 lanes x 16B = 256B row). Each warp instruction
// serves both nodes (shfl source = j + (lane&16); LDG.128 loads two rows).
// ~4.3 instr/edge vs ~7 in the 1-node/warp version (issue-bound kernel).
// Short half contributes w=0 dummy edges for the imbalance region.
// Grid-stride at full residency. Zeroes g_count (invariant).
// ---------------------------------------------------------------------------
__global__ __launch_bounds__(256) void gather_kernel(const float* __restrict__ h) {
    int warp = threadIdx.x >> 5;
    int lane = threadIdx.x & 31;
    int hl   = lane & 15;            // lane within half-warp
    int hsel = lane & 16;            // 0 for node 2p, 16 for node 2p+1
    const float4* __restrict__ h4 = reinterpret_cast<const float4*>(h);

    int gw = blockIdx.x * 8 + warp;
    int nwarps = gridDim.x * 8;
    const int npairs = N_NODES / 2;  // 25000 (N even)

    for (int p = gw; p < npairs; p += nwarps) {
        int n = p * 2 + (hsel >> 4);     // this half's node
        int beg = g_start[n];
        int cnt = g_count[n];
        int cntmax = max(cnt, __shfl_xor_sync(0xffffffffu, cnt, 16));

        float4 acc = make_float4(0.f, 0.f, 0.f, 0.f);

        for (int base = 0; base < cntmax; base += 16) {
            // half-parallel rec load: lane hl holds rec base+hl of its node
            int   rs = 0;
            float rw = 0.f;
            if (base + hl < cnt) {
                EdgeRec r = g_edge[beg + base + hl];
                rs = r.s;
                rw = r.w;
            }
            int mm = cntmax - base;
            if (mm > 16) mm = 16;
            int j = 0;
            for (; j + 3 < mm; j += 4) {
                int   s0 = __shfl_sync(0xffffffffu, rs, j     + hsel);
                int   s1 = __shfl_sync(0xffffffffu, rs, j + 1 + hsel);
                int   s2 = __shfl_sync(0xffffffffu, rs, j + 2 + hsel);
                int   s3 = __shfl_sync(0xffffffffu, rs, j + 3 + hsel);
                float w0 = __shfl_sync(0xffffffffu, rw, j     + hsel);
                float w1 = __shfl_sync(0xffffffffu, rw, j + 1 + hsel);
                float w2 = __shfl_sync(0xffffffffu, rw, j + 2 + hsel);
                float w3 = __shfl_sync(0xffffffffu, rw, j + 3 + hsel);
                float4 a0 = h4[(size_t)s0 * 16 + hl];
                float4 a1 = h4[(size_t)s1 * 16 + hl];
                float4 a2 = h4[(size_t)s2 * 16 + hl];
                float4 a3 = h4[(size_t)s3 * 16 + hl];
                acc.x += a0.x * w0 + a1.x * w1 + a2.x * w2 + a3.x * w3;
                acc.y += a0.y * w0 + a1.y * w1 + a2.y * w2 + a3.y * w3;
                acc.z += a0.z * w0 + a1.z * w1 + a2.z * w2 + a3.z * w3;
                acc.w += a0.w * w0 + a1.w * w1 + a2.w * w2 + a3.w * w3;
            }
            for (; j < mm; j++) {
                int   s0 = __shfl_sync(0xffffffffu, rs, j + hsel);
                float w0 = __shfl_sync(0xffffffffu, rw, j + hsel);
                float4 a0 = h4[(size_t)s0 * 16 + hl];
                acc.x += a0.x * w0;
                acc.y += a0.y * w0;
                acc.z += a0.z * w0;
                acc.w += a0.w * w0;
            }
        }

        float inv = 1.0f / fmaxf((float)cnt, 1.0f);
        reinterpret_cast<float4*>(g_hn)[(size_t)n * 16 + hl] =
            make_float4(acc.x * inv, acc.y * inv, acc.z * inv, acc.w * inv);
        if (hl == 0) g_count[n] = 0;
    }
}

// ---------------------------------------------------------------------------
// K5: HMMA GEMM: out[tile 128, 64] = [h|h_N] @ W^T + b, bf16 3-split.
// ---------------------------------------------------------------------------
__global__ __launch_bounds__(256)
void gemm_kernel(const float* __restrict__ h,
                 const float* __restrict__ W,
                 const float* __restrict__ b,
                 float* __restrict__ out) {
    extern __shared__ char smem[];
    uint32_t sb = s2u(smem);
    int tid = threadIdx.x;
    int wid = tid >> 5;
    int lane = tid & 31;
    int n0 = blockIdx.x * TILE_M;

    // ---- stage B (W -> Bh/Bm) ----
    #pragma unroll
    for (int it = 0; it < 4; it++) {
        int task = tid + 256 * it;
        int r = task >> 4;
        int c = task & 15;
        float v[8];
        const float4* p = reinterpret_cast<const float4*>(W + (size_t)r * D2 + c * 8);
        float4 v0 = p[0], v1 = p[1];
        v[0]=v0.x; v[1]=v0.y; v[2]=v0.z; v[3]=v0.w;
        v[4]=v1.x; v[5]=v1.y; v[6]=v1.z; v[7]=v1.w;
        uint4 uh, um; split8(v, uh, um);
        uint32_t off = (uint32_t)r * ASTRIDE + c * 16;
        *reinterpret_cast<uint4*>(smem + SM_BH + off) = uh;
        *reinterpret_cast<uint4*>(smem + SM_BM + off) = um;
    }

    // ---- stage A ([h|h_N] -> Ah/Am) ----
    #pragma unroll
    for (int it = 0; it < 8; it++) {
        int task = tid + 256 * it;
        int r = task >> 4;
        int c = task & 15;
        int n = n0 + r;
        float v[8];
        if (n < N_NODES) {
            const float* srcp = (c < 8)
                ? (h    + (size_t)n * D + c * 8)
                : (g_hn + (size_t)n * D + (c - 8) * 8);
            const float4* p = reinterpret_cast<const float4*>(srcp);
            float4 v0 = p[0], v1 = p[1];
            v[0]=v0.x; v[1]=v0.y; v[2]=v0.z; v[3]=v0.w;
            v[4]=v1.x; v[5]=v1.y; v[6]=v1.z; v[7]=v1.w;
        } else {
            #pragma unroll
            for (int i = 0; i < 8; i++) v[i] = 0.f;
        }
        uint4 uh, um; split8(v, uh, um);
        uint32_t off = (uint32_t)r * ASTRIDE + c * 16;
        *reinterpret_cast<uint4*>(smem + SM_AH + off) = uh;
        *reinterpret_cast<uint4*>(smem + SM_AM + off) = um;
    }
    __syncthreads();

    // ---- compute ----
    float c[8][4];
    #pragma unroll
    for (int nc = 0; nc < 8; nc++)
        #pragma unroll
        for (int i = 0; i < 4; i++) c[nc][i] = 0.f;

    uint32_t arow = (lane & 7) + ((lane >> 3) & 1) * 8;
    uint32_t asel = (lane >> 4) * 16;
    uint32_t brow = lane & 7;
    uint32_t bsel = ((lane >> 3) & 1) * 16;

    #pragma unroll
    for (int ks = 0; ks < 8; ks++) {
        uint32_t acol = ks * 32 + asel;
        uint32_t aaddr = sb + SM_AH + (wid * 16 + arow) * ASTRIDE + acol;
        uint32_t ah[4], am[4];
        ldm_x4(ah[0], ah[1], ah[2], ah[3], aaddr);
        ldm_x4(am[0], am[1], am[2], am[3], aaddr + (SM_AM - SM_AH));

        uint32_t bcol = ks * 32 + bsel;
        #pragma unroll
        for (int nc = 0; nc < 8; nc++) {
            uint32_t baddr = sb + SM_BH + (nc * 8 + brow) * ASTRIDE + bcol;
            uint32_t bh0, bh1, bm0, bm1;
            ldm_x2(bh0, bh1, baddr);
            ldm_x2(bm0, bm1, baddr + (SM_BM - SM_BH));
            mma16816(c[nc], ah, bh0, bh1);   // hh
            mma16816(c[nc], ah, bm0, bm1);   // hm
            mma16816(c[nc], am, bh0, bh1);   // mh
        }
    }

    // ---- epilogue: bias + store ----
    int r0 = n0 + wid * 16 + (lane >> 2);
    int r1 = r0 + 8;
    int cb = (lane & 3) * 2;
    #pragma unroll
    for (int nc = 0; nc < 8; nc++) {
        int col = nc * 8 + cb;
        float2 bv = *reinterpret_cast<const float2*>(b + col);
        if (r0 < N_NODES)
            *reinterpret_cast<float2*>(out + (size_t)r0 * D + col) =
                make_float2(c[nc][0] + bv.x, c[nc][1] + bv.y);
        if (r1 < N_NODES)
            *reinterpret_cast<float2*>(out + (size_t)r1 * D + col) =
                make_float2(c[nc][2] + bv.x, c[nc][3] + bv.y);
    }
}

// ---------------------------------------------------------------------------
// Launch — 5 kernels
// ---------------------------------------------------------------------------
extern "C" void kernel_launch(void* const* d_in, const int* in_sizes, int n_in,
                              void* d_out, int out_size) {
    const float* h   = (const float*)d_in[0];
    const float* w   = (const float*)d_in[1];
    const int*   src = (const int*)  d_in[2];
    const int*   dst = (const int*)  d_in[3];
    const float* W   = (const float*)d_in[4];
    const float* b   = (const float*)d_in[5];
    float* out = (float*)d_out;

    (void)in_sizes; (void)n_in; (void)out_size;

    static bool attr_set = false;
    if (!attr_set) {
        cudaFuncSetAttribute(gemm_kernel,
                             cudaFuncAttributeMaxDynamicSharedMemorySize, SM_TOTAL);
        attr_set = true;
    }

    hist_kernel<<<(N_EDGES / 4 + 255) / 256, 256>>>(dst);
    reserve_kernel<<<NBLK_SCAN, SCAN_BLK>>>();
    pos_kernel<<<(N_EDGES / 4 + 255) / 256, 256>>>(src, dst, w);
    gather_kernel<<<GATHER_BLOCKS, 256>>>(h);
    gemm_kernel<<<N_TILES, 256, SM_TOTAL>>>(h, W, b, out);
}